// round 1
// baseline (speedup 1.0000x reference)
#include <cuda_runtime.h>
#include <math.h>

#define B_  2
#define S_  2048
#define E_  1024
#define H_  16
#define HD_ 64
#define M_  (B_*S_)   // 4096

// Scratch (allocation-free rule: __device__ globals)
__device__ float g_Q[B_*S_*E_];
__device__ float g_K[B_*S_*E_];
__device__ float g_V[B_*S_*E_];
__device__ float g_ctx[B_*S_*E_];   // laid out as [B][H][S][HD] == reference reshape

// ============================================================
// SGEMM: C[M,N] = A[M,K] @ W[N,K]^T + bias[N]
// 128x128 block, BK=8, 256 threads, 8x8 microtile
// ============================================================
__device__ __forceinline__ void sgemm_body(const float* __restrict__ A,
                                           const float* __restrict__ W,
                                           const float* __restrict__ bias,
                                           float* __restrict__ C,
                                           int M, int N, int K)
{
    __shared__ float As[8][128];
    __shared__ float Bs[8][128];

    const int tid = threadIdx.x;
    const int tx  = tid & 15;
    const int ty  = tid >> 4;
    const int bm  = blockIdx.y * 128;
    const int bn  = blockIdx.x * 128;

    // loaders: 2 threads per row, float4 each
    const int lr = tid >> 1;          // 0..127
    const int lc = (tid & 1) * 4;     // 0 or 4
    const float* Ap = A + (size_t)(bm + lr) * K + lc;
    const float* Wp = W + (size_t)(bn + lr) * K + lc;

    float acc[8][8];
#pragma unroll
    for (int i = 0; i < 8; i++)
#pragma unroll
        for (int j = 0; j < 8; j++) acc[i][j] = 0.f;

    for (int k0 = 0; k0 < K; k0 += 8) {
        float4 av = *(const float4*)(Ap + k0);
        float4 wv = *(const float4*)(Wp + k0);
        As[lc + 0][lr] = av.x; As[lc + 1][lr] = av.y;
        As[lc + 2][lr] = av.z; As[lc + 3][lr] = av.w;
        Bs[lc + 0][lr] = wv.x; Bs[lc + 1][lr] = wv.y;
        Bs[lc + 2][lr] = wv.z; Bs[lc + 3][lr] = wv.w;
        __syncthreads();

#pragma unroll
        for (int kk = 0; kk < 8; kk++) {
            float ar[8], br[8];
            *(float4*)&ar[0] = *(const float4*)&As[kk][ty * 4];
            *(float4*)&ar[4] = *(const float4*)&As[kk][64 + ty * 4];
            *(float4*)&br[0] = *(const float4*)&Bs[kk][tx * 4];
            *(float4*)&br[4] = *(const float4*)&Bs[kk][64 + tx * 4];
#pragma unroll
            for (int i = 0; i < 8; i++)
#pragma unroll
                for (int j = 0; j < 8; j++)
                    acc[i][j] += ar[i] * br[j];
        }
        __syncthreads();
    }

    // epilogue: rows {ty*4+i, 64+ty*4+i}, cols {tx*4+j, 64+tx*4+j}
#pragma unroll
    for (int i = 0; i < 8; i++) {
        int row = bm + ((i < 4) ? (ty * 4 + i) : (64 + ty * 4 + (i - 4)));
        float* Cp = C + (size_t)row * N + bn;
#pragma unroll
        for (int jh = 0; jh < 2; jh++) {
            int col = jh * 64 + tx * 4;
            float4 o;
            o.x = acc[i][jh * 4 + 0] + bias[bn + col + 0];
            o.y = acc[i][jh * 4 + 1] + bias[bn + col + 1];
            o.z = acc[i][jh * 4 + 2] + bias[bn + col + 2];
            o.w = acc[i][jh * 4 + 3] + bias[bn + col + 3];
            *(float4*)(Cp + col) = o;
        }
    }
}

__global__ __launch_bounds__(256) void qkv_kernel(
    const float* __restrict__ X,
    const float* __restrict__ Wq, const float* __restrict__ bq,
    const float* __restrict__ Wk, const float* __restrict__ bk,
    const float* __restrict__ Wv, const float* __restrict__ bv)
{
    const float* W; const float* bias; float* C;
    if (blockIdx.z == 0)      { W = Wq; bias = bq; C = g_Q; }
    else if (blockIdx.z == 1) { W = Wk; bias = bk; C = g_K; }
    else                      { W = Wv; bias = bv; C = g_V; }
    sgemm_body(X, W, bias, C, M_, E_, E_);
}

__global__ __launch_bounds__(256) void oproj_kernel(
    const float* __restrict__ Wo, const float* __restrict__ bo,
    float* __restrict__ out)
{
    sgemm_body(g_ctx, Wo, bo, out, M_, E_, E_);
}

// ============================================================
// Flash attention: one block per (b, h, 64-query-row tile)
// 256 threads; 4x4 microtile over (row, col) / (row, d)
// smem (dynamic 64KB): Qt[64][64] (d-major), Kt[64][64] (d-major),
//                      Ps[64][64], Vs[64][64]
// ============================================================
__global__ __launch_bounds__(256) void attn_kernel()
{
    extern __shared__ float sm[];
    float* Qt = sm;                // [d][m]  64*64
    float* Kt = sm + 64 * 64;      // [d][n]
    float* Ps = sm + 2 * 64 * 64;  // [m][n]
    float* Vs = sm + 3 * 64 * 64;  // [n][d]

    const int b  = blockIdx.z;
    const int h  = blockIdx.y;
    const int q0 = blockIdx.x * 64;
    const int tid = threadIdx.x;
    const int tx = tid & 15;       // d-col / key-col group
    const int ty = tid >> 4;       // query-row group (lane-contiguous per 16)

    const float* Qg = g_Q + (size_t)b * S_ * E_ + (size_t)h * HD_;
    const float* Kg = g_K + (size_t)b * S_ * E_ + (size_t)h * HD_;
    const float* Vg = g_V + (size_t)b * S_ * E_ + (size_t)h * HD_;

    // ---- load Q tile transposed, pre-scaled by 1/sqrt(HD) ----
    {
        const int m   = tid & 63;   // warp covers m 0..31 -> all 32 banks on store
        const int d4b = tid >> 6;
#pragma unroll
        for (int it = 0; it < 4; ++it) {
            int d4 = d4b + it * 4;
            float4 v = *(const float4*)(Qg + (size_t)(q0 + m) * E_ + d4 * 4);
            Qt[(d4 * 4 + 0) * 64 + m] = v.x * 0.125f;
            Qt[(d4 * 4 + 1) * 64 + m] = v.y * 0.125f;
            Qt[(d4 * 4 + 2) * 64 + m] = v.z * 0.125f;
            Qt[(d4 * 4 + 3) * 64 + m] = v.w * 0.125f;
        }
    }

    float m_run[4], l_run[4], acc[4][4];
#pragma unroll
    for (int i = 0; i < 4; i++) {
        m_run[i] = -INFINITY; l_run[i] = 0.f;
#pragma unroll
        for (int j = 0; j < 4; j++) acc[i][j] = 0.f;
    }

    for (int kt = 0; kt < 32; ++kt) {
        __syncthreads();   // previous PV reads of Kt/Vs/Ps done; Qt ready (kt=0)

        // ---- load K tile transposed ----
        {
            const int m   = tid & 63;
            const int d4b = tid >> 6;
            const int kr  = kt * 64 + m;
#pragma unroll
            for (int it = 0; it < 4; ++it) {
                int d4 = d4b + it * 4;
                float4 v = *(const float4*)(Kg + (size_t)kr * E_ + d4 * 4);
                Kt[(d4 * 4 + 0) * 64 + m] = v.x;
                Kt[(d4 * 4 + 1) * 64 + m] = v.y;
                Kt[(d4 * 4 + 2) * 64 + m] = v.z;
                Kt[(d4 * 4 + 3) * 64 + m] = v.w;
            }
        }
        // ---- load V tile straight [n][d] ----
        {
            const int j   = tid >> 2;     // 0..63
            const int d4b = tid & 3;
#pragma unroll
            for (int it = 0; it < 4; ++it) {
                int d4 = d4b + it * 4;
                float4 v = *(const float4*)(Vg + (size_t)(kt * 64 + j) * E_ + d4 * 4);
                *(float4*)&Vs[j * 64 + d4 * 4] = v;
            }
        }
        __syncthreads();

        // ---- scores: s[i][j] = sum_d Qt[d][ty*4+i] * Kt[d][tx*4+j] ----
        float s[4][4];
#pragma unroll
        for (int i = 0; i < 4; i++)
#pragma unroll
            for (int j = 0; j < 4; j++) s[i][j] = 0.f;

#pragma unroll 8
        for (int d = 0; d < 64; ++d) {
            float4 qa = *(const float4*)&Qt[d * 64 + ty * 4];
            float4 kb = *(const float4*)&Kt[d * 64 + tx * 4];
            float ar[4] = {qa.x, qa.y, qa.z, qa.w};
            float br[4] = {kb.x, kb.y, kb.z, kb.w};
#pragma unroll
            for (int i = 0; i < 4; i++)
#pragma unroll
                for (int j = 0; j < 4; j++)
                    s[i][j] += ar[i] * br[j];
        }

        // ---- online softmax (rows spread over 16 contiguous lanes) ----
#pragma unroll
        for (int i = 0; i < 4; i++) {
            float mt = fmaxf(fmaxf(s[i][0], s[i][1]), fmaxf(s[i][2], s[i][3]));
            mt = fmaxf(mt, __shfl_xor_sync(0xffffffffu, mt, 1));
            mt = fmaxf(mt, __shfl_xor_sync(0xffffffffu, mt, 2));
            mt = fmaxf(mt, __shfl_xor_sync(0xffffffffu, mt, 4));
            mt = fmaxf(mt, __shfl_xor_sync(0xffffffffu, mt, 8));
            float mn   = fmaxf(m_run[i], mt);
            float corr = __expf(m_run[i] - mn);   // 0 on first tile (-inf)
            m_run[i] = mn;
            float rs = 0.f;
#pragma unroll
            for (int j = 0; j < 4; j++) {
                s[i][j] = __expf(s[i][j] - mn);
                rs += s[i][j];
            }
            rs += __shfl_xor_sync(0xffffffffu, rs, 1);
            rs += __shfl_xor_sync(0xffffffffu, rs, 2);
            rs += __shfl_xor_sync(0xffffffffu, rs, 4);
            rs += __shfl_xor_sync(0xffffffffu, rs, 8);
            l_run[i] = l_run[i] * corr + rs;
#pragma unroll
            for (int j = 0; j < 4; j++) acc[i][j] *= corr;
            *(float4*)&Ps[(ty * 4 + i) * 64 + tx * 4] =
                make_float4(s[i][0], s[i][1], s[i][2], s[i][3]);
        }
        __syncthreads();

        // ---- PV: acc[i][d] += sum_j Ps[row][j] * Vs[j][d] ----
#pragma unroll 4
        for (int j4 = 0; j4 < 16; ++j4) {
            float pav[4][4];
#pragma unroll
            for (int i = 0; i < 4; i++)
                *(float4*)&pav[i][0] = *(const float4*)&Ps[(ty * 4 + i) * 64 + j4 * 4];
#pragma unroll
            for (int jj = 0; jj < 4; ++jj) {
                float4 vb = *(const float4*)&Vs[(j4 * 4 + jj) * 64 + tx * 4];
#pragma unroll
                for (int i = 0; i < 4; i++) {
                    acc[i][0] += pav[i][jj] * vb.x;
                    acc[i][1] += pav[i][jj] * vb.y;
                    acc[i][2] += pav[i][jj] * vb.z;
                    acc[i][3] += pav[i][jj] * vb.w;
                }
            }
        }
    }

    // ---- epilogue: ctx in [B][H][S][HD] layout (== reference reshape) ----
#pragma unroll
    for (int i = 0; i < 4; i++) {
        float inv = 1.0f / l_run[i];
        int srow = q0 + ty * 4 + i;
        float* Op = g_ctx + (((size_t)b * H_ + h) * S_ + srow) * HD_ + tx * 4;
        *(float4*)Op = make_float4(acc[i][0] * inv, acc[i][1] * inv,
                                   acc[i][2] * inv, acc[i][3] * inv);
    }
}

// ============================================================
extern "C" void kernel_launch(void* const* d_in, const int* in_sizes, int n_in,
                              void* d_out, int out_size)
{
    const float* X  = (const float*)d_in[0];
    const float* Wq = (const float*)d_in[1];
    const float* bq = (const float*)d_in[2];
    const float* Wk = (const float*)d_in[3];
    const float* bk = (const float*)d_in[4];
    const float* Wv = (const float*)d_in[5];
    const float* bv = (const float*)d_in[6];
    const float* Wo = (const float*)d_in[7];
    const float* bo = (const float*)d_in[8];
    float* out = (float*)d_out;

    // Q/K/V projections (grid.z selects matrix)
    qkv_kernel<<<dim3(E_ / 128, M_ / 128, 3), 256>>>(X, Wq, bq, Wk, bk, Wv, bv);

    // attention
    const int attn_smem = 4 * 64 * 64 * (int)sizeof(float);  // 64 KB dynamic
    cudaFuncSetAttribute(attn_kernel,
                         cudaFuncAttributeMaxDynamicSharedMemorySize, attn_smem);
    attn_kernel<<<dim3(S_ / 64, H_, B_), 256, attn_smem>>>();

    // output projection
    oproj_kernel<<<dim3(E_ / 128, M_ / 128), 256>>>(Wo, bo, out);
}

// round 5
// speedup vs baseline: 1.9745x; 1.9745x over previous
#include <cuda_runtime.h>
#include <math.h>
#include <stdint.h>

#define B_  2
#define S_  2048
#define E_  1024
#define H_  16
#define HD_ 64
#define M_  (B_*S_)   // 4096

// Scratch (allocation-free rule: __device__ globals)
__device__ float g_Q[B_*S_*E_];
__device__ float g_K[B_*S_*E_];
__device__ float g_V[B_*S_*E_];
__device__ float g_ctx[B_*S_*E_];   // [B][H][S][HD] == reference reshape order

// ============================================================
// helpers
// ============================================================
__device__ __forceinline__ float tf32r(float x) {
    uint32_t u;
    asm("cvt.rna.tf32.f32 %0, %1;" : "=r"(u) : "f"(x));
    return __uint_as_float(u);
}

// D += A(16x8) * B(8x8), tf32 inputs, f32 accum
__device__ __forceinline__ void mma8(float c[4],
                                     uint32_t a0, uint32_t a1, uint32_t a2, uint32_t a3,
                                     uint32_t b0, uint32_t b1) {
    asm volatile(
        "mma.sync.aligned.m16n8k8.row.col.f32.tf32.tf32.f32 "
        "{%0,%1,%2,%3}, {%4,%5,%6,%7}, {%8,%9}, {%0,%1,%2,%3};"
        : "+f"(c[0]), "+f"(c[1]), "+f"(c[2]), "+f"(c[3])
        : "r"(a0), "r"(a1), "r"(a2), "r"(a3), "r"(b0), "r"(b1));
}

__device__ __forceinline__ uint32_t fau(float x) { return __float_as_uint(x); }

// ============================================================
// tf32 mma.sync GEMM: C[4096,1024] = A[4096,1024] @ W[1024,1024]^T + bias
// 128x128 tile, BK=16, 256 threads (8 warps, 2x4), 4x4 m16n8k8 per warp
// smem k-major, stride 136 floats (conflict-free frag loads)
// ============================================================
#define GPAD 136
#define GNKT 64   // 1024 / 16

__device__ __forceinline__ void gemm128_mma(const float* __restrict__ A,
                                            const float* __restrict__ W,
                                            const float* __restrict__ bias,
                                            float* __restrict__ C)
{
    __shared__ float As[2][16][GPAD];
    __shared__ float Bs[2][16][GPAD];

    const int tid  = threadIdx.x;
    const int lane = tid & 31;
    const int wid  = tid >> 5;
    const int g    = lane >> 2;
    const int tig  = lane & 3;
    const int warp_m = wid >> 2;       // 0..1 -> 64 rows
    const int warp_n = wid & 3;        // 0..3 -> 32 cols
    const int bm = blockIdx.y * 128;
    const int bn = blockIdx.x * 128;

    const int lm  = tid & 63;          // loader row within half
    const int lk  = (tid >> 6) * 4;    // loader k offset 0,4,8,12

    float acc[4][4][4];
#pragma unroll
    for (int mi = 0; mi < 4; mi++)
#pragma unroll
        for (int nt = 0; nt < 4; nt++)
#pragma unroll
            for (int j = 0; j < 4; j++) acc[mi][nt][j] = 0.f;

    float4 ra[2], rb[2];

    // ---- preload tile 0 ----
#pragma unroll
    for (int it = 0; it < 2; it++) {
        int row = it * 64 + lm;
        ra[it] = *(const float4*)(A + (size_t)(bm + row) * E_ + lk);
        rb[it] = *(const float4*)(W + (size_t)(bn + row) * E_ + lk);
    }
#pragma unroll
    for (int it = 0; it < 2; it++) {
        int row = it * 64 + lm;
        As[0][lk + 0][row] = tf32r(ra[it].x); As[0][lk + 1][row] = tf32r(ra[it].y);
        As[0][lk + 2][row] = tf32r(ra[it].z); As[0][lk + 3][row] = tf32r(ra[it].w);
        Bs[0][lk + 0][row] = tf32r(rb[it].x); Bs[0][lk + 1][row] = tf32r(rb[it].y);
        Bs[0][lk + 2][row] = tf32r(rb[it].z); Bs[0][lk + 3][row] = tf32r(rb[it].w);
    }
    __syncthreads();

    for (int kt = 0; kt < GNKT; ++kt) {
        const int buf = kt & 1;
        const bool more = (kt + 1 < GNKT);

        if (more) {
            const int k0 = (kt + 1) * 16 + lk;
#pragma unroll
            for (int it = 0; it < 2; it++) {
                int row = it * 64 + lm;
                ra[it] = *(const float4*)(A + (size_t)(bm + row) * E_ + k0);
                rb[it] = *(const float4*)(W + (size_t)(bn + row) * E_ + k0);
            }
        }

        // compute: 2 k8 steps x (4 m-tiles x 4 n-tiles)
#pragma unroll
        for (int ks = 0; ks < 2; ks++) {
            const int k0 = ks * 8;
            uint32_t af[4][4];
#pragma unroll
            for (int mi = 0; mi < 4; mi++) {
                const int m0 = warp_m * 64 + mi * 16;
                af[mi][0] = fau(As[buf][k0 + tig    ][m0 + g]);
                af[mi][1] = fau(As[buf][k0 + tig    ][m0 + g + 8]);
                af[mi][2] = fau(As[buf][k0 + tig + 4][m0 + g]);
                af[mi][3] = fau(As[buf][k0 + tig + 4][m0 + g + 8]);
            }
#pragma unroll
            for (int nt = 0; nt < 4; nt++) {
                const int n0 = warp_n * 32 + nt * 8;
                uint32_t b0 = fau(Bs[buf][k0 + tig    ][n0 + g]);
                uint32_t b1 = fau(Bs[buf][k0 + tig + 4][n0 + g]);
#pragma unroll
                for (int mi = 0; mi < 4; mi++)
                    mma8(acc[mi][nt], af[mi][0], af[mi][1], af[mi][2], af[mi][3], b0, b1);
            }
        }

        if (more) {
            const int nb = buf ^ 1;
#pragma unroll
            for (int it = 0; it < 2; it++) {
                int row = it * 64 + lm;
                As[nb][lk + 0][row] = tf32r(ra[it].x); As[nb][lk + 1][row] = tf32r(ra[it].y);
                As[nb][lk + 2][row] = tf32r(ra[it].z); As[nb][lk + 3][row] = tf32r(ra[it].w);
                Bs[nb][lk + 0][row] = tf32r(rb[it].x); Bs[nb][lk + 1][row] = tf32r(rb[it].y);
                Bs[nb][lk + 2][row] = tf32r(rb[it].z); Bs[nb][lk + 3][row] = tf32r(rb[it].w);
            }
            __syncthreads();
        }
    }

    // ---- epilogue ----
#pragma unroll
    for (int mi = 0; mi < 4; mi++) {
        const int r0 = bm + warp_m * 64 + mi * 16 + g;
#pragma unroll
        for (int nt = 0; nt < 4; nt++) {
            const int col = bn + warp_n * 32 + nt * 8 + 2 * tig;
            float bx = bias[col], by = bias[col + 1];
            float2 v0 = make_float2(acc[mi][nt][0] + bx, acc[mi][nt][1] + by);
            float2 v1 = make_float2(acc[mi][nt][2] + bx, acc[mi][nt][3] + by);
            *(float2*)(C + (size_t)r0 * E_ + col)       = v0;
            *(float2*)(C + (size_t)(r0 + 8) * E_ + col) = v1;
        }
    }
}

__global__ __launch_bounds__(256) void qkv_kernel(
    const float* __restrict__ X,
    const float* __restrict__ Wq, const float* __restrict__ bq,
    const float* __restrict__ Wk, const float* __restrict__ bk,
    const float* __restrict__ Wv, const float* __restrict__ bv)
{
    const float* W; const float* bias; float* C;
    if (blockIdx.z == 0)      { W = Wq; bias = bq; C = g_Q; }
    else if (blockIdx.z == 1) { W = Wk; bias = bk; C = g_K; }
    else                      { W = Wv; bias = bv; C = g_V; }
    gemm128_mma(X, W, bias, C);
}

__global__ __launch_bounds__(256) void oproj_kernel(
    const float* __restrict__ Wo, const float* __restrict__ bo,
    float* __restrict__ out)
{
    gemm128_mma(g_ctx, Wo, bo, out);
}

// ============================================================
// Flash attention with mma.sync tf32
// 128-query x 64-key tiles, 256 threads (8 warps), warp = 16 rows x 64 cols
// smem: Qs [64][136] d-major, Kt [64][72] d-major, Vs [64][72] key-major,
//       Ps [128][68]
// ============================================================
#define QP 136
#define KP 72
#define VP 72
#define PP 68
#define ATTN_SMEM ((64*QP + 64*KP + 64*VP + 128*PP) * (int)sizeof(float))

__global__ __launch_bounds__(256) void attn_kernel()
{
    extern __shared__ float sm[];
    float* Qs = sm;                    // [d][m]
    float* Kt = Qs + 64 * QP;          // [d][n]
    float* Vs = Kt + 64 * KP;          // [key][d]
    float* Ps = Vs + 64 * VP;          // [m][key]

    const int b  = blockIdx.z;
    const int h  = blockIdx.y;
    const int q0 = blockIdx.x * 128;
    const int tid  = threadIdx.x;
    const int lane = tid & 31;
    const int wid  = tid >> 5;
    const int g    = lane >> 2;
    const int tig  = lane & 3;
    const int r0   = wid * 16 + g;     // warp-local query row (and r0+8)

    const float* Qg = g_Q + (size_t)b * S_ * E_ + (size_t)h * HD_;
    const float* Kg = g_K + (size_t)b * S_ * E_ + (size_t)h * HD_;
    const float* Vg = g_V + (size_t)b * S_ * E_ + (size_t)h * HD_;

    // ---- load Q tile transposed [d][m], scaled by 1/8, tf32-rounded ----
    {
        const int m  = tid & 127;
        const int dc = (tid >> 7) * 4;   // 0 or 4
#pragma unroll
        for (int it = 0; it < 8; ++it) {
            const int d0 = it * 8 + dc;
            float4 v = *(const float4*)(Qg + (size_t)(q0 + m) * E_ + d0);
            Qs[(d0 + 0) * QP + m] = tf32r(v.x * 0.125f);
            Qs[(d0 + 1) * QP + m] = tf32r(v.y * 0.125f);
            Qs[(d0 + 2) * QP + m] = tf32r(v.z * 0.125f);
            Qs[(d0 + 3) * QP + m] = tf32r(v.w * 0.125f);
        }
    }

    float mr0 = -INFINITY, mr1 = -INFINITY, lr0 = 0.f, lr1 = 0.f;
    float oa[8][4];
#pragma unroll
    for (int nt = 0; nt < 8; nt++)
#pragma unroll
        for (int j = 0; j < 4; j++) oa[nt][j] = 0.f;

    for (int kt = 0; kt < 32; ++kt) {
        __syncthreads();   // prior tile's S/PV reads of Kt/Vs done (Q ready at kt=0)

        // ---- K tile transposed [d][n] ----
        {
            const int n  = tid & 63;
            const int dc = (tid >> 6) * 4;   // 0,4,8,12
            const int kr = kt * 64 + n;
#pragma unroll
            for (int it = 0; it < 4; ++it) {
                const int d0 = it * 16 + dc;
                float4 v = *(const float4*)(Kg + (size_t)kr * E_ + d0);
                Kt[(d0 + 0) * KP + n] = tf32r(v.x);
                Kt[(d0 + 1) * KP + n] = tf32r(v.y);
                Kt[(d0 + 2) * KP + n] = tf32r(v.z);
                Kt[(d0 + 3) * KP + n] = tf32r(v.w);
            }
        }
        // ---- V tile [key][d] ----
        {
            const int key = tid >> 2;
            const int dc  = (tid & 3) * 4;
            const int kr  = kt * 64 + key;
#pragma unroll
            for (int it = 0; it < 4; ++it) {
                const int d0 = it * 16 + dc;
                float4 v = *(const float4*)(Vg + (size_t)kr * E_ + d0);
                Vs[key * VP + d0 + 0] = tf32r(v.x);
                Vs[key * VP + d0 + 1] = tf32r(v.y);
                Vs[key * VP + d0 + 2] = tf32r(v.z);
                Vs[key * VP + d0 + 3] = tf32r(v.w);
            }
        }
        __syncthreads();

        // ---- S = Q K^T : warp computes 16 x 64 via 8 n-tiles x 8 k-steps ----
        float sc[8][4];
#pragma unroll
        for (int nt = 0; nt < 8; nt++)
#pragma unroll
            for (int j = 0; j < 4; j++) sc[nt][j] = 0.f;

#pragma unroll
        for (int ks = 0; ks < 8; ks++) {
            const int k0 = ks * 8;
            const int mB = wid * 16;
            uint32_t a0 = fau(Qs[(k0 + tig    ) * QP + mB + g]);
            uint32_t a1 = fau(Qs[(k0 + tig    ) * QP + mB + g + 8]);
            uint32_t a2 = fau(Qs[(k0 + tig + 4) * QP + mB + g]);
            uint32_t a3 = fau(Qs[(k0 + tig + 4) * QP + mB + g + 8]);
#pragma unroll
            for (int nt = 0; nt < 8; nt++) {
                uint32_t b0 = fau(Kt[(k0 + tig    ) * KP + nt * 8 + g]);
                uint32_t b1 = fau(Kt[(k0 + tig + 4) * KP + nt * 8 + g]);
                mma8(sc[nt], a0, a1, a2, a3, b0, b1);
            }
        }

        // ---- online softmax on C-fragment layout ----
        float mx0 = -INFINITY, mx1 = -INFINITY;
#pragma unroll
        for (int nt = 0; nt < 8; nt++) {
            mx0 = fmaxf(mx0, fmaxf(sc[nt][0], sc[nt][1]));
            mx1 = fmaxf(mx1, fmaxf(sc[nt][2], sc[nt][3]));
        }
        mx0 = fmaxf(mx0, __shfl_xor_sync(0xffffffffu, mx0, 1));
        mx0 = fmaxf(mx0, __shfl_xor_sync(0xffffffffu, mx0, 2));
        mx1 = fmaxf(mx1, __shfl_xor_sync(0xffffffffu, mx1, 1));
        mx1 = fmaxf(mx1, __shfl_xor_sync(0xffffffffu, mx1, 2));

        const float mn0 = fmaxf(mr0, mx0);
        const float mn1 = fmaxf(mr1, mx1);
        const float c0 = __expf(mr0 - mn0);
        const float c1 = __expf(mr1 - mn1);
        mr0 = mn0; mr1 = mn1;

        float rs0 = 0.f, rs1 = 0.f;
#pragma unroll
        for (int nt = 0; nt < 8; nt++) {
            sc[nt][0] = __expf(sc[nt][0] - mn0); rs0 += sc[nt][0];
            sc[nt][1] = __expf(sc[nt][1] - mn0); rs0 += sc[nt][1];
            sc[nt][2] = __expf(sc[nt][2] - mn1); rs1 += sc[nt][2];
            sc[nt][3] = __expf(sc[nt][3] - mn1); rs1 += sc[nt][3];
        }
        rs0 += __shfl_xor_sync(0xffffffffu, rs0, 1);
        rs0 += __shfl_xor_sync(0xffffffffu, rs0, 2);
        rs1 += __shfl_xor_sync(0xffffffffu, rs1, 1);
        rs1 += __shfl_xor_sync(0xffffffffu, rs1, 2);
        lr0 = lr0 * c0 + rs0;
        lr1 = lr1 * c1 + rs1;

#pragma unroll
        for (int nt = 0; nt < 8; nt++) {
            oa[nt][0] *= c0; oa[nt][1] *= c0;
            oa[nt][2] *= c1; oa[nt][3] *= c1;
        }

        // ---- P -> smem (warp-local rows only) ----
#pragma unroll
        for (int nt = 0; nt < 8; nt++) {
            const int cc = nt * 8 + 2 * tig;
            Ps[(r0    ) * PP + cc    ] = tf32r(sc[nt][0]);
            Ps[(r0    ) * PP + cc + 1] = tf32r(sc[nt][1]);
            Ps[(r0 + 8) * PP + cc    ] = tf32r(sc[nt][2]);
            Ps[(r0 + 8) * PP + cc + 1] = tf32r(sc[nt][3]);
        }
        __syncwarp();

        // ---- PV: oa += P @ V ----
#pragma unroll
        for (int ks = 0; ks < 8; ks++) {
            const int k0 = ks * 8;
            uint32_t a0 = fau(Ps[(r0    ) * PP + k0 + tig]);
            uint32_t a1 = fau(Ps[(r0 + 8) * PP + k0 + tig]);
            uint32_t a2 = fau(Ps[(r0    ) * PP + k0 + tig + 4]);
            uint32_t a3 = fau(Ps[(r0 + 8) * PP + k0 + tig + 4]);
#pragma unroll
            for (int nt = 0; nt < 8; nt++) {
                uint32_t b0 = fau(Vs[(k0 + tig    ) * VP + nt * 8 + g]);
                uint32_t b1 = fau(Vs[(k0 + tig + 4) * VP + nt * 8 + g]);
                mma8(oa[nt], a0, a1, a2, a3, b0, b1);
            }
        }
        __syncwarp();   // PV reads of Ps done before next-tile overwrite
    }

    // ---- epilogue: ctx[b][h][s][d] ----
    const float i0 = 1.0f / lr0;
    const float i1 = 1.0f / lr1;
    float* Og = g_ctx + ((size_t)(b * H_ + h) * S_ + q0) * HD_;
#pragma unroll
    for (int nt = 0; nt < 8; nt++) {
        const int col = nt * 8 + 2 * tig;
        *(float2*)(Og + (size_t)(r0    ) * HD_ + col) =
            make_float2(oa[nt][0] * i0, oa[nt][1] * i0);
        *(float2*)(Og + (size_t)(r0 + 8) * HD_ + col) =
            make_float2(oa[nt][2] * i1, oa[nt][3] * i1);
    }
}

// ============================================================
extern "C" void kernel_launch(void* const* d_in, const int* in_sizes, int n_in,
                              void* d_out, int out_size)
{
    const float* X  = (const float*)d_in[0];
    const float* Wq = (const float*)d_in[1];
    const float* bq = (const float*)d_in[2];
    const float* Wk = (const float*)d_in[3];
    const float* bk = (const float*)d_in[4];
    const float* Wv = (const float*)d_in[5];
    const float* bv = (const float*)d_in[6];
    const float* Wo = (const float*)d_in[7];
    const float* bo = (const float*)d_in[8];
    float* out = (float*)d_out;

    // Q/K/V projections (tf32 mma.sync)
    qkv_kernel<<<dim3(E_ / 128, M_ / 128, 3), 256>>>(X, Wq, bq, Wk, bk, Wv, bv);

    // attention (tf32 mma.sync flash)
    cudaFuncSetAttribute(attn_kernel,
                         cudaFuncAttributeMaxDynamicSharedMemorySize, ATTN_SMEM);
    attn_kernel<<<dim3(S_ / 128, H_, B_), 256, ATTN_SMEM>>>();

    // output projection
    oproj_kernel<<<dim3(E_ / 128, M_ / 128), 256>>>(Wo, bo, out);
}

// round 7
// speedup vs baseline: 3.0712x; 1.5555x over previous
#include <cuda_runtime.h>
#include <math.h>
#include <stdint.h>

#define B_  2
#define S_  2048
#define E_  1024
#define H_  16
#define HD_ 64
#define M_  (B_*S_)   // 4096

// Scratch (allocation-free rule: __device__ globals)
__device__ float g_Q[B_*S_*E_];
__device__ float g_K[B_*S_*E_];
__device__ float g_V[B_*S_*E_];
__device__ float g_ctx[B_*S_*E_];   // [B][H][S][HD] == reference reshape order

// ============================================================
// helpers
// ============================================================
__device__ __forceinline__ float tf32r(float x) {
    uint32_t u;
    asm("cvt.rna.tf32.f32 %0, %1;" : "=r"(u) : "f"(x));
    return __uint_as_float(u);
}

__device__ __forceinline__ void mma8(float c[4],
                                     uint32_t a0, uint32_t a1, uint32_t a2, uint32_t a3,
                                     uint32_t b0, uint32_t b1) {
    asm volatile(
        "mma.sync.aligned.m16n8k8.row.col.f32.tf32.tf32.f32 "
        "{%0,%1,%2,%3}, {%4,%5,%6,%7}, {%8,%9}, {%0,%1,%2,%3};"
        : "+f"(c[0]), "+f"(c[1]), "+f"(c[2]), "+f"(c[3])
        : "r"(a0), "r"(a1), "r"(a2), "r"(a3), "r"(b0), "r"(b1));
}

__device__ __forceinline__ void ldmx4(uint32_t r[4], uint32_t addr) {
    asm volatile("ldmatrix.sync.aligned.m8n8.x4.shared.b16 {%0,%1,%2,%3}, [%4];"
                 : "=r"(r[0]), "=r"(r[1]), "=r"(r[2]), "=r"(r[3]) : "r"(addr));
}

__device__ __forceinline__ uint32_t smem_u32(const void* p) {
    uint32_t a;
    asm("{ .reg .u64 t; cvta.to.shared.u64 t, %1; cvt.u32.u64 %0, t; }"
        : "=r"(a) : "l"(p));
    return a;
}

// A-fragment (row-major [m][k], stride ST floats) ldmatrix lane offset:
//   lanes 0-15: row (l&15), k +0 ; lanes 16-31: row (l&15), k +4
// B-fragment ([n][k], two n8 tiles): lanes0-7 n+l,k0; 8-15 n+(l-8),k0+4;
//   16-23 n+8+(l-16),k0; 24-31 n+8+(l-24),k0+4
#define ALANE(lane, ST) ((((lane) & 15) * (ST) + ((lane) >> 4) * 4) * 4)
#define BLANE(lane, ST) (((((lane) >> 4) * 8 + ((lane) & 7)) * (ST) + (((lane) >> 3) & 1) * 4) * 4)

// ============================================================
// tf32 mma.sync GEMM: C[4096,1024] = A @ W^T + bias
// 128x128 tile, BK=16, 256 threads (8 warps 2x4), 4x4 m16n8k8 per warp
// smem row-major [row][k], stride 20 floats; ldmatrix fragment loads
// ============================================================
#define GST  20
#define GBUF (128 * GST)            // floats per buffer per matrix
#define GNKT 64                     // 1024 / 16

__device__ __forceinline__ void gemm128_mma(const float* __restrict__ A,
                                            const float* __restrict__ W,
                                            const float* __restrict__ bias,
                                            float* __restrict__ C)
{
    __shared__ float As[2 * GBUF];
    __shared__ float Bs[2 * GBUF];

    const int tid  = threadIdx.x;
    const int lane = tid & 31;
    const int wid  = tid >> 5;
    const int g    = lane >> 2;
    const int tig  = lane & 3;
    const int warp_m = wid >> 2;       // 0..1 -> 64 rows
    const int warp_n = wid & 3;        // 0..3 -> 32 cols
    const int bm = blockIdx.y * 128;
    const int bn = blockIdx.x * 128;

    // loader: 4 threads per row (f4 = tid&3), 64 rows per pass, 2 passes
    const int lrow = tid >> 2;         // 0..63
    const int lf4  = (tid & 3) * 4;    // k float offset 0,4,8,12

    const uint32_t sAs = smem_u32(As);
    const uint32_t sBs = smem_u32(Bs);
    const uint32_t aL = sAs + (uint32_t)(warp_m * 64 * GST * 4) + ALANE(lane, GST);
    const uint32_t bL = sBs + (uint32_t)(warp_n * 32 * GST * 4) + BLANE(lane, GST);
    const uint32_t BUFB = GBUF * 4;

    float acc[4][4][4];
#pragma unroll
    for (int mi = 0; mi < 4; mi++)
#pragma unroll
        for (int nt = 0; nt < 4; nt++)
#pragma unroll
            for (int j = 0; j < 4; j++) acc[mi][nt][j] = 0.f;

    const float* Ap = A + (size_t)bm * E_ + lf4;
    const float* Wp = W + (size_t)bn * E_ + lf4;

    float4 ra[2], rb[2];
#pragma unroll
    for (int p = 0; p < 2; p++) {
        const int row = p * 64 + lrow;
        ra[p] = *(const float4*)(Ap + (size_t)row * E_);
        rb[p] = *(const float4*)(Wp + (size_t)row * E_);
    }
#pragma unroll
    for (int p = 0; p < 2; p++) {
        const int row = p * 64 + lrow;
        *(float4*)&As[row * GST + lf4] =
            make_float4(tf32r(ra[p].x), tf32r(ra[p].y), tf32r(ra[p].z), tf32r(ra[p].w));
        *(float4*)&Bs[row * GST + lf4] =
            make_float4(tf32r(rb[p].x), tf32r(rb[p].y), tf32r(rb[p].z), tf32r(rb[p].w));
    }
    __syncthreads();

    for (int kt = 0; kt < GNKT; ++kt) {
        const int buf = kt & 1;
        const bool more = (kt + 1 < GNKT);

        if (more) {
            const int k0 = (kt + 1) * 16;
#pragma unroll
            for (int p = 0; p < 2; p++) {
                const int row = p * 64 + lrow;
                ra[p] = *(const float4*)(Ap + (size_t)row * E_ + k0);
                rb[p] = *(const float4*)(Wp + (size_t)row * E_ + k0);
            }
        }

        const uint32_t aB = aL + buf * BUFB;
        const uint32_t bB = bL + buf * BUFB;
#pragma unroll
        for (int ks = 0; ks < 2; ks++) {
            uint32_t af[4][4];
#pragma unroll
            for (int mi = 0; mi < 4; mi++)
                ldmx4(af[mi], aB + mi * (16 * GST * 4) + ks * 32);
            uint32_t bf[2][4];
#pragma unroll
            for (int np = 0; np < 2; np++)
                ldmx4(bf[np], bB + np * (16 * GST * 4) + ks * 32);
#pragma unroll
            for (int np = 0; np < 2; np++)
#pragma unroll
                for (int hh = 0; hh < 2; hh++) {
                    const int nt = np * 2 + hh;
#pragma unroll
                    for (int mi = 0; mi < 4; mi++)
                        mma8(acc[mi][nt], af[mi][0], af[mi][1], af[mi][2], af[mi][3],
                             bf[np][hh * 2], bf[np][hh * 2 + 1]);
                }
        }

        if (more) {
            const int nb = buf ^ 1;
#pragma unroll
            for (int p = 0; p < 2; p++) {
                const int row = p * 64 + lrow;
                *(float4*)&As[nb * GBUF + row * GST + lf4] =
                    make_float4(tf32r(ra[p].x), tf32r(ra[p].y), tf32r(ra[p].z), tf32r(ra[p].w));
                *(float4*)&Bs[nb * GBUF + row * GST + lf4] =
                    make_float4(tf32r(rb[p].x), tf32r(rb[p].y), tf32r(rb[p].z), tf32r(rb[p].w));
            }
            __syncthreads();
        }
    }

    // ---- epilogue ----
#pragma unroll
    for (int mi = 0; mi < 4; mi++) {
        const int r0 = bm + warp_m * 64 + mi * 16 + g;
#pragma unroll
        for (int nt = 0; nt < 4; nt++) {
            const int col = bn + warp_n * 32 + nt * 8 + 2 * tig;
            float bx = bias[col], by = bias[col + 1];
            *(float2*)(C + (size_t)r0 * E_ + col) =
                make_float2(acc[mi][nt][0] + bx, acc[mi][nt][1] + by);
            *(float2*)(C + (size_t)(r0 + 8) * E_ + col) =
                make_float2(acc[mi][nt][2] + bx, acc[mi][nt][3] + by);
        }
    }
}

__global__ __launch_bounds__(256, 2) void qkv_kernel(
    const float* __restrict__ X,
    const float* __restrict__ Wq, const float* __restrict__ bq,
    const float* __restrict__ Wk, const float* __restrict__ bk,
    const float* __restrict__ Wv, const float* __restrict__ bv)
{
    const float* W; const float* bias; float* C;
    if (blockIdx.z == 0)      { W = Wq; bias = bq; C = g_Q; }
    else if (blockIdx.z == 1) { W = Wk; bias = bk; C = g_K; }
    else                      { W = Wv; bias = bv; C = g_V; }
    gemm128_mma(X, W, bias, C);
}

__global__ __launch_bounds__(256, 2) void oproj_kernel(
    const float* __restrict__ Wo, const float* __restrict__ bo,
    float* __restrict__ out)
{
    gemm128_mma(g_ctx, Wo, bo, out);
}

// ============================================================
// Flash attention, tf32 mma.sync + ldmatrix
// 128-query x 64-key tiles, 256 threads (8 warps), warp = 16 rows x 64 cols
// smem (all stride 68): Qs[128][.] row-major [m][d], Kt[64][.] [key][d]
// (natural K layout IS the B-operand layout), Vt[64][.] [d][key], Ps[128][.]
// ============================================================
#define AP 68
#define ATTN_SMEM ((128 + 64 + 64 + 128) * AP * (int)sizeof(float))

__global__ __launch_bounds__(256, 2) void attn_kernel()
{
    extern __shared__ float sm[];
    float* Qs = sm;                    // [m][d]
    float* Kt = Qs + 128 * AP;         // [key][d]  == B-operand [n][k]
    float* Vt = Kt + 64 * AP;          // [d][key]  == B-operand [n][k]
    float* Ps = Vt + 64 * AP;          // [m][key]

    const int b  = blockIdx.z;
    const int h  = blockIdx.y;
    const int q0 = blockIdx.x * 128;
    const int tid  = threadIdx.x;
    const int lane = tid & 31;
    const int wid  = tid >> 5;
    const int g    = lane >> 2;
    const int tig  = lane & 3;
    const int r0   = wid * 16 + g;

    const uint32_t sQ = smem_u32(Qs);
    const uint32_t sK = smem_u32(Kt);
    const uint32_t sV = smem_u32(Vt);
    const uint32_t sP = smem_u32(Ps);
    const uint32_t qL = sQ + (uint32_t)(wid * 16 * AP * 4) + ALANE(lane, AP);
    const uint32_t pL = sP + (uint32_t)(wid * 16 * AP * 4) + ALANE(lane, AP);
    const uint32_t kL = sK + BLANE(lane, AP);
    const uint32_t vL = sV + BLANE(lane, AP);

    const float* Qg = g_Q + (size_t)b * S_ * E_ + (size_t)h * HD_;
    const float* Kg = g_K + (size_t)b * S_ * E_ + (size_t)h * HD_;
    const float* Vg = g_V + (size_t)b * S_ * E_ + (size_t)h * HD_;

    // ---- Q tile [m][d], scaled, tf32 ----
    {
        const int f4 = (tid & 15) * 4;
        const int rr = tid >> 4;       // 16 rows per pass
#pragma unroll
        for (int p = 0; p < 8; ++p) {
            const int row = p * 16 + rr;
            float4 v = *(const float4*)(Qg + (size_t)(q0 + row) * E_ + f4);
            *(float4*)&Qs[row * AP + f4] =
                make_float4(tf32r(v.x * 0.125f), tf32r(v.y * 0.125f),
                            tf32r(v.z * 0.125f), tf32r(v.w * 0.125f));
        }
    }

    float mr0 = -INFINITY, mr1 = -INFINITY, lr0 = 0.f, lr1 = 0.f;
    float oa[8][4];
#pragma unroll
    for (int nt = 0; nt < 8; nt++)
#pragma unroll
        for (int j = 0; j < 4; j++) oa[nt][j] = 0.f;

    for (int kt = 0; kt < 32; ++kt) {
        __syncthreads();   // prior tile's reads of Kt/Vt done (Qs ready at kt=0)

        // ---- K tile straight copy [key][d] ----
        {
            const int f4 = (tid & 15) * 4;
            const int rr = tid >> 4;
#pragma unroll
            for (int p = 0; p < 4; ++p) {
                const int key = p * 16 + rr;
                float4 v = *(const float4*)(Kg + (size_t)(kt * 64 + key) * E_ + f4);
                *(float4*)&Kt[key * AP + f4] =
                    make_float4(tf32r(v.x), tf32r(v.y), tf32r(v.z), tf32r(v.w));
            }
        }
        // ---- V tile transposed [d][key] (conflict-free: lanes = consecutive keys) ----
        {
            const int key = tid & 63;
            const int dg  = tid >> 6;       // 0..3
            const float* Vr = Vg + (size_t)(kt * 64 + key) * E_;
#pragma unroll
            for (int it = 0; it < 4; ++it) {
                const int d0 = it * 16 + dg * 4;
                float4 v = *(const float4*)(Vr + d0);
                Vt[(d0 + 0) * AP + key] = tf32r(v.x);
                Vt[(d0 + 1) * AP + key] = tf32r(v.y);
                Vt[(d0 + 2) * AP + key] = tf32r(v.z);
                Vt[(d0 + 3) * AP + key] = tf32r(v.w);
            }
        }
        __syncthreads();

        // ---- S = Q K^T : 8 ks x (1 A-ldmatrix + 4 B-ldmatrix + 8 mma) ----
        float sc[8][4];
#pragma unroll
        for (int nt = 0; nt < 8; nt++)
#pragma unroll
            for (int j = 0; j < 4; j++) sc[nt][j] = 0.f;

#pragma unroll
        for (int ks = 0; ks < 8; ks++) {
            uint32_t aq[4];
            ldmx4(aq, qL + ks * 32);
#pragma unroll
            for (int np = 0; np < 4; np++) {
                uint32_t bf[4];
                ldmx4(bf, kL + np * (16 * AP * 4) + ks * 32);
                mma8(sc[np * 2    ], aq[0], aq[1], aq[2], aq[3], bf[0], bf[1]);
                mma8(sc[np * 2 + 1], aq[0], aq[1], aq[2], aq[3], bf[2], bf[3]);
            }
        }

        // ---- online softmax on C-fragment layout ----
        float mx0 = -INFINITY, mx1 = -INFINITY;
#pragma unroll
        for (int nt = 0; nt < 8; nt++) {
            mx0 = fmaxf(mx0, fmaxf(sc[nt][0], sc[nt][1]));
            mx1 = fmaxf(mx1, fmaxf(sc[nt][2], sc[nt][3]));
        }
        mx0 = fmaxf(mx0, __shfl_xor_sync(0xffffffffu, mx0, 1));
        mx0 = fmaxf(mx0, __shfl_xor_sync(0xffffffffu, mx0, 2));
        mx1 = fmaxf(mx1, __shfl_xor_sync(0xffffffffu, mx1, 1));
        mx1 = fmaxf(mx1, __shfl_xor_sync(0xffffffffu, mx1, 2));

        const float mn0 = fmaxf(mr0, mx0);
        const float mn1 = fmaxf(mr1, mx1);
        const float c0 = __expf(mr0 - mn0);
        const float c1 = __expf(mr1 - mn1);
        mr0 = mn0; mr1 = mn1;

        float rs0 = 0.f, rs1 = 0.f;
#pragma unroll
        for (int nt = 0; nt < 8; nt++) {
            sc[nt][0] = __expf(sc[nt][0] - mn0); rs0 += sc[nt][0];
            sc[nt][1] = __expf(sc[nt][1] - mn0); rs0 += sc[nt][1];
            sc[nt][2] = __expf(sc[nt][2] - mn1); rs1 += sc[nt][2];
            sc[nt][3] = __expf(sc[nt][3] - mn1); rs1 += sc[nt][3];
        }
        rs0 += __shfl_xor_sync(0xffffffffu, rs0, 1);
        rs0 += __shfl_xor_sync(0xffffffffu, rs0, 2);
        rs1 += __shfl_xor_sync(0xffffffffu, rs1, 1);
        rs1 += __shfl_xor_sync(0xffffffffu, rs1, 2);
        lr0 = lr0 * c0 + rs0;
        lr1 = lr1 * c1 + rs1;

#pragma unroll
        for (int nt = 0; nt < 8; nt++) {
            oa[nt][0] *= c0; oa[nt][1] *= c0;
            oa[nt][2] *= c1; oa[nt][3] *= c1;
        }

        // ---- P -> smem (warp-local rows only) ----
#pragma unroll
        for (int nt = 0; nt < 8; nt++) {
            const int cc = nt * 8 + 2 * tig;
            *(float2*)&Ps[(r0    ) * AP + cc] = make_float2(tf32r(sc[nt][0]), tf32r(sc[nt][1]));
            *(float2*)&Ps[(r0 + 8) * AP + cc] = make_float2(tf32r(sc[nt][2]), tf32r(sc[nt][3]));
        }
        __syncwarp();

        // ---- PV: oa += P @ V ----
#pragma unroll
        for (int ks = 0; ks < 8; ks++) {
            uint32_t ap[4];
            ldmx4(ap, pL + ks * 32);
#pragma unroll
            for (int np = 0; np < 4; np++) {
                uint32_t bf[4];
                ldmx4(bf, vL + np * (16 * AP * 4) + ks * 32);
                mma8(oa[np * 2    ], ap[0], ap[1], ap[2], ap[3], bf[0], bf[1]);
                mma8(oa[np * 2 + 1], ap[0], ap[1], ap[2], ap[3], bf[2], bf[3]);
            }
        }
        __syncwarp();   // PV reads of Ps done before next-tile overwrite
    }

    // ---- epilogue: ctx[b][h][s][d] ----
    const float i0 = 1.0f / lr0;
    const float i1 = 1.0f / lr1;
    float* Og = g_ctx + ((size_t)(b * H_ + h) * S_ + q0) * HD_;
#pragma unroll
    for (int nt = 0; nt < 8; nt++) {
        const int col = nt * 8 + 2 * tig;
        *(float2*)(Og + (size_t)(r0    ) * HD_ + col) =
            make_float2(oa[nt][0] * i0, oa[nt][1] * i0);
        *(float2*)(Og + (size_t)(r0 + 8) * HD_ + col) =
            make_float2(oa[nt][2] * i1, oa[nt][3] * i1);
    }
}

// ============================================================
extern "C" void kernel_launch(void* const* d_in, const int* in_sizes, int n_in,
                              void* d_out, int out_size)
{
    const float* X  = (const float*)d_in[0];
    const float* Wq = (const float*)d_in[1];
    const float* bq = (const float*)d_in[2];
    const float* Wk = (const float*)d_in[3];
    const float* bk = (const float*)d_in[4];
    const float* Wv = (const float*)d_in[5];
    const float* bv = (const float*)d_in[6];
    const float* Wo = (const float*)d_in[7];
    const float* bo = (const float*)d_in[8];
    float* out = (float*)d_out;

    qkv_kernel<<<dim3(E_ / 128, M_ / 128, 3), 256>>>(X, Wq, bq, Wk, bk, Wv, bv);

    cudaFuncSetAttribute(attn_kernel,
                         cudaFuncAttributeMaxDynamicSharedMemorySize, ATTN_SMEM);
    attn_kernel<<<dim3(S_ / 128, H_, B_), 256, ATTN_SMEM>>>();

    oproj_kernel<<<dim3(E_ / 128, M_ / 128), 256>>>(Wo, bo, out);
}

// round 10
// speedup vs baseline: 3.4393x; 1.1199x over previous
#include <cuda_runtime.h>
#include <math.h>
#include <stdint.h>

#define B_  2
#define S_  2048
#define E_  1024
#define H_  16
#define HD_ 64
#define M_  (B_*S_)   // 4096

// Scratch (allocation-free rule: __device__ globals)
__device__ float g_Xr[M_*E_];        // tf32-rounded X
__device__ float g_Wr[4][E_*E_];     // tf32-rounded Wq,Wk,Wv,Wo
__device__ float g_Q[B_*S_*E_];      // rounded + 0.125-scaled
__device__ float g_K[B_*S_*E_];      // rounded
__device__ float g_Vt[B_*H_*HD_*S_]; // rounded, [b][h][d][s]
__device__ float g_ctx[B_*S_*E_];    // rounded, [B][H][S][HD] order

// ============================================================
// helpers
// ============================================================
__device__ __forceinline__ float tf32r(float x) {
    uint32_t u;
    asm("cvt.rna.tf32.f32 %0, %1;" : "=r"(u) : "f"(x));
    return __uint_as_float(u);
}

__device__ __forceinline__ void mma8(float c[4],
                                     uint32_t a0, uint32_t a1, uint32_t a2, uint32_t a3,
                                     uint32_t b0, uint32_t b1) {
    asm volatile(
        "mma.sync.aligned.m16n8k8.row.col.f32.tf32.tf32.f32 "
        "{%0,%1,%2,%3}, {%4,%5,%6,%7}, {%8,%9}, {%0,%1,%2,%3};"
        : "+f"(c[0]), "+f"(c[1]), "+f"(c[2]), "+f"(c[3])
        : "r"(a0), "r"(a1), "r"(a2), "r"(a3), "r"(b0), "r"(b1));
}

__device__ __forceinline__ void ldmx4(uint32_t r[4], uint32_t addr) {
    asm volatile("ldmatrix.sync.aligned.m8n8.x4.shared.b16 {%0,%1,%2,%3}, [%4];"
                 : "=r"(r[0]), "=r"(r[1]), "=r"(r[2]), "=r"(r[3]) : "r"(addr));
}

__device__ __forceinline__ uint32_t smem_u32(const void* p) {
    uint32_t a;
    asm("{ .reg .u64 t; cvta.to.shared.u64 t, %1; cvt.u32.u64 %0, t; }"
        : "=r"(a) : "l"(p));
    return a;
}

__device__ __forceinline__ void cpasync16(uint32_t dst, const float* src) {
    asm volatile(
        "{ .reg .u64 g; cvta.to.global.u64 g, %1; "
        "cp.async.cg.shared.global [%0], [g], 16; }"
        :: "r"(dst), "l"(src) : "memory");
}
#define CP_COMMIT() asm volatile("cp.async.commit_group;" ::: "memory")
#define CP_WAIT0()  asm volatile("cp.async.wait_group 0;" ::: "memory")
#define CP_WAIT2()  asm volatile("cp.async.wait_group 2;" ::: "memory")

// ldmatrix lane->address maps (stride ST floats)
#define ALANE(lane, ST) ((((lane) & 15) * (ST) + ((lane) >> 4) * 4) * 4)
#define BLANE(lane, ST) (((((lane) >> 4) * 8 + ((lane) & 7)) * (ST) + (((lane) >> 3) & 1) * 4) * 4)

// ============================================================
// prepass: tf32-round X and the 4 weights into scratch
// ============================================================
__global__ __launch_bounds__(256) void prep_kernel(
    const float* __restrict__ X,
    const float* __restrict__ Wq, const float* __restrict__ Wk,
    const float* __restrict__ Wv, const float* __restrict__ Wo)
{
    const int seg = blockIdx.y;
    const float* src; float* dst; int n;
    if (seg == 0)      { src = X;  dst = g_Xr;    n = M_ * E_; }
    else if (seg == 1) { src = Wq; dst = g_Wr[0]; n = E_ * E_; }
    else if (seg == 2) { src = Wk; dst = g_Wr[1]; n = E_ * E_; }
    else if (seg == 3) { src = Wv; dst = g_Wr[2]; n = E_ * E_; }
    else               { src = Wo; dst = g_Wr[3]; n = E_ * E_; }
    const int i = (blockIdx.x * 256 + threadIdx.x) * 4;
    if (i < n) {
        float4 v = *(const float4*)(src + i);
        *(float4*)(dst + i) =
            make_float4(tf32r(v.x), tf32r(v.y), tf32r(v.z), tf32r(v.w));
    }
}

// ============================================================
// GEMM core: 128x128 tile, BK=16, 4-stage cp.async pipeline,
// 256 threads (8 warps 2x4), 4x4 m16n8k8 per warp, ldmatrix frags
// ============================================================
#define GST    20
#define GBUF   (128 * GST)         // floats per stage per matrix
#define GBUFB  (GBUF * 4)          // 10240 bytes
#define GSTAGES 4
#define GEMM_SMEM (GSTAGES * 2 * GBUFB)   // 81920 bytes
#define GNKT   64

__device__ __forceinline__ void gemm_core(const float* __restrict__ A,
                                          const float* __restrict__ W,
                                          float* smem,
                                          float acc[4][4][4],
                                          int bm, int bn)
{
    float* As = smem;
    float* Bs = smem + GSTAGES * GBUF;

    const int tid  = threadIdx.x;
    const int lane = tid & 31;
    const int wid  = tid >> 5;
    const int warp_m = wid >> 2;
    const int warp_n = wid & 3;

    const int lrow = tid >> 2;          // 0..63
    const int lf4  = (tid & 3) * 4;     // 0,4,8,12

    const uint32_t sA = smem_u32(As);
    const uint32_t sB = smem_u32(Bs);
    const uint32_t aL = sA + (uint32_t)(warp_m * 64 * GST * 4) + ALANE(lane, GST);
    const uint32_t bL = sB + (uint32_t)(warp_n * 32 * GST * 4) + BLANE(lane, GST);
    const uint32_t dA = sA + (uint32_t)((lrow * GST + lf4) * 4);
    const uint32_t dB = sB + (uint32_t)((lrow * GST + lf4) * 4);

    const float* Ap = A + (size_t)(bm + lrow) * E_ + lf4;
    const float* Wp = W + (size_t)(bn + lrow) * E_ + lf4;

#pragma unroll
    for (int mi = 0; mi < 4; mi++)
#pragma unroll
        for (int nt = 0; nt < 4; nt++)
#pragma unroll
            for (int j = 0; j < 4; j++) acc[mi][nt][j] = 0.f;

    // prologue: issue stages 0..2
#pragma unroll
    for (int s = 0; s < GSTAGES - 1; ++s) {
        const int k0 = s * 16;
#pragma unroll
        for (int p = 0; p < 2; p++) {
            cpasync16(dA + s * GBUFB + p * (64 * GST * 4), Ap + (size_t)p * 64 * E_ + k0);
            cpasync16(dB + s * GBUFB + p * (64 * GST * 4), Wp + (size_t)p * 64 * E_ + k0);
        }
        CP_COMMIT();
    }

    for (int kt = 0; kt < GNKT; ++kt) {
        CP_WAIT2();            // tile kt resident
        __syncthreads();       // all warps past compute(kt-1); data published

        {   // issue tile kt+3 into stage (kt+3)&3 (empty commit at tail keeps counts)
            const int t = kt + GSTAGES - 1;
            if (t < GNKT) {
                const int st = t & 3;
                const int k0 = t * 16;
#pragma unroll
                for (int p = 0; p < 2; p++) {
                    cpasync16(dA + st * GBUFB + p * (64 * GST * 4), Ap + (size_t)p * 64 * E_ + k0);
                    cpasync16(dB + st * GBUFB + p * (64 * GST * 4), Wp + (size_t)p * 64 * E_ + k0);
                }
            }
            CP_COMMIT();
        }

        const uint32_t aB = aL + (kt & 3) * GBUFB;
        const uint32_t bB = bL + (kt & 3) * GBUFB;
#pragma unroll
        for (int ks = 0; ks < 2; ks++) {
            uint32_t af[4][4];
#pragma unroll
            for (int mi = 0; mi < 4; mi++)
                ldmx4(af[mi], aB + mi * (16 * GST * 4) + ks * 32);
            uint32_t bf[2][4];
#pragma unroll
            for (int np = 0; np < 2; np++)
                ldmx4(bf[np], bB + np * (16 * GST * 4) + ks * 32);
#pragma unroll
            for (int np = 0; np < 2; np++)
#pragma unroll
                for (int hh = 0; hh < 2; hh++) {
                    const int nt = np * 2 + hh;
#pragma unroll
                    for (int mi = 0; mi < 4; mi++)
                        mma8(acc[mi][nt], af[mi][0], af[mi][1], af[mi][2], af[mi][3],
                             bf[np][hh * 2], bf[np][hh * 2 + 1]);
                }
        }
    }
}

// ============================================================
// qkv: X @ W^T + b -> Q (rounded, *0.125) / K (rounded) / Vt (rounded, transposed)
// ============================================================
__global__ __launch_bounds__(256, 2) void qkv_kernel(
    const float* __restrict__ bq, const float* __restrict__ bk,
    const float* __restrict__ bv)
{
    extern __shared__ float smem[];
    const int z = blockIdx.z;
    const float* bias = (z == 0) ? bq : (z == 1) ? bk : bv;
    const int bm = blockIdx.y * 128;
    const int bn = blockIdx.x * 128;

    float acc[4][4][4];
    gemm_core(g_Xr, g_Wr[z], smem, acc, bm, bn);

    const int lane = threadIdx.x & 31;
    const int wid  = threadIdx.x >> 5;
    const int g    = lane >> 2;
    const int tig  = lane & 3;
    const int warp_m = wid >> 2;
    const int warp_n = wid & 3;

    if (z < 2) {
        float* C = (z == 0) ? g_Q : g_K;
        const float scale = (z == 0) ? 0.125f : 1.0f;
#pragma unroll
        for (int mi = 0; mi < 4; mi++) {
            const int r0 = bm + warp_m * 64 + mi * 16 + g;
#pragma unroll
            for (int nt = 0; nt < 4; nt++) {
                const int col = bn + warp_n * 32 + nt * 8 + 2 * tig;
                float bx = bias[col], by = bias[col + 1];
                *(float2*)(C + (size_t)r0 * E_ + col) =
                    make_float2(tf32r(acc[mi][nt][0] + bx) * scale,
                                tf32r(acc[mi][nt][1] + by) * scale);
                *(float2*)(C + (size_t)(r0 + 8) * E_ + col) =
                    make_float2(tf32r(acc[mi][nt][2] + bx) * scale,
                                tf32r(acc[mi][nt][3] + by) * scale);
            }
        }
    } else {
        // V: transposed rounded store into g_Vt[b][h][d][s]
#pragma unroll
        for (int mi = 0; mi < 4; mi++) {
            const int r0 = bm + warp_m * 64 + mi * 16 + g;
#pragma unroll
            for (int nt = 0; nt < 4; nt++) {
                const int col = bn + warp_n * 32 + nt * 8 + 2 * tig;
                float bx = bias[col], by = bias[col + 1];
#pragma unroll
                for (int rr = 0; rr < 2; rr++) {
                    const int row = r0 + rr * 8;
                    const int s  = row & (S_ - 1);
                    const int bb = row >> 11;
                    float v0 = tf32r(acc[mi][nt][rr * 2 + 0] + bx);
                    float v1 = tf32r(acc[mi][nt][rr * 2 + 1] + by);
                    const int h0 = col >> 6, d0 = col & 63;
                    const int h1 = (col + 1) >> 6, d1 = (col + 1) & 63;
                    g_Vt[(((size_t)bb * H_ + h0) * HD_ + d0) * S_ + s] = v0;
                    g_Vt[(((size_t)bb * H_ + h1) * HD_ + d1) * S_ + s] = v1;
                }
            }
        }
    }
}

// ============================================================
// oproj: ctx @ Wo^T + bo -> out (fp32)
// ============================================================
__global__ __launch_bounds__(256, 2) void oproj_kernel(
    const float* __restrict__ bo, float* __restrict__ out)
{
    extern __shared__ float smem[];
    const int bm = blockIdx.y * 128;
    const int bn = blockIdx.x * 128;

    float acc[4][4][4];
    gemm_core(g_ctx, g_Wr[3], smem, acc, bm, bn);

    const int lane = threadIdx.x & 31;
    const int wid  = threadIdx.x >> 5;
    const int g    = lane >> 2;
    const int tig  = lane & 3;
    const int warp_m = wid >> 2;
    const int warp_n = wid & 3;

#pragma unroll
    for (int mi = 0; mi < 4; mi++) {
        const int r0 = bm + warp_m * 64 + mi * 16 + g;
#pragma unroll
        for (int nt = 0; nt < 4; nt++) {
            const int col = bn + warp_n * 32 + nt * 8 + 2 * tig;
            float bx = bo[col], by = bo[col + 1];
            *(float2*)(out + (size_t)r0 * E_ + col) =
                make_float2(acc[mi][nt][0] + bx, acc[mi][nt][1] + by);
            *(float2*)(out + (size_t)(r0 + 8) * E_ + col) =
                make_float2(acc[mi][nt][2] + bx, acc[mi][nt][3] + by);
        }
    }
}

// ============================================================
// Flash attention: cp.async double-buffered K/V, hoisted Q frags
// 128-query x 64-key tiles, 256 threads (8 warps), warp = 16 rows x 64 cols
// smem: Kb[2][64][68], Vb[2][64][68], QP[128][68] (Q then Ps, warp-local alias)
// ============================================================
#define AP    68
#define KVB   (64 * AP)           // floats per K/V buffer
#define KVBB  (KVB * 4)           // 17408 bytes
#define ATTN_SMEM ((4 * KVB + 128 * AP) * (int)sizeof(float))   // 104448

__global__ __launch_bounds__(256, 2) void attn_kernel()
{
    extern __shared__ float sm[];
    float* Kb = sm;                 // [2][64][AP]
    float* Vb = sm + 2 * KVB;       // [2][64][AP]  (rows = d, cols = key)
    float* QP = sm + 4 * KVB;       // [128][AP]    Q tile then Ps

    const int b  = blockIdx.z;
    const int h  = blockIdx.y;
    const int q0 = blockIdx.x * 128;
    const int tid  = threadIdx.x;
    const int lane = tid & 31;
    const int wid  = tid >> 5;
    const int g    = lane >> 2;
    const int tig  = lane & 3;
    const int r0   = wid * 16 + g;

    const uint32_t sKb = smem_u32(Kb);
    const uint32_t sVb = smem_u32(Vb);
    const uint32_t sQP = smem_u32(QP);
    const uint32_t qpL = sQP + (uint32_t)(wid * 16 * AP * 4) + ALANE(lane, AP);

    const float* Qg  = g_Q + (size_t)b * S_ * E_ + (size_t)h * HD_;
    const float* Kg  = g_K + (size_t)b * S_ * E_ + (size_t)h * HD_;
    const float* Vtg = g_Vt + (size_t)(b * H_ + h) * HD_ * S_;

    // cp.async loader mapping for K/V tiles
    const int lrow = tid >> 2;            // 0..63 (key for K, d for V)
    const int lc0  = (tid & 3) * 16;      // float offset base; 4 chunks of 4
    const uint32_t dK = sKb + (uint32_t)((lrow * AP + lc0) * 4);
    const uint32_t dV = sVb + (uint32_t)((lrow * AP + lc0) * 4);

    // ---- Q tile fill (already rounded+scaled in gmem) ----
    {
        const int f4 = (tid & 15) * 4;
        const int rr = tid >> 4;
#pragma unroll
        for (int p = 0; p < 8; ++p) {
            const int row = p * 16 + rr;
            *(float4*)&QP[row * AP + f4] =
                *(const float4*)(Qg + (size_t)(q0 + row) * E_ + f4);
        }
    }

    // ---- issue tile 0 ----
    {
        const float* Ks = Kg + (size_t)lrow * E_;           // key row, tile 0
        const float* Vs = Vtg + (size_t)lrow * S_;          // d row, tile 0
#pragma unroll
        for (int i = 0; i < 4; i++) {
            cpasync16(dK + i * 16, Ks + lc0 + i * 4);
            cpasync16(dV + i * 16, Vs + lc0 + i * 4);
        }
        CP_COMMIT();
    }

    __syncthreads();   // Q tile visible

    // ---- hoist Q fragments (warp-local region of QP) ----
    uint32_t qf[8][4];
#pragma unroll
    for (int ks = 0; ks < 8; ks++) ldmx4(qf[ks], qpL + ks * 32);

    float mr0 = -INFINITY, mr1 = -INFINITY, lr0 = 0.f, lr1 = 0.f;
    float oa[8][4];
#pragma unroll
    for (int nt = 0; nt < 8; nt++)
#pragma unroll
        for (int j = 0; j < 4; j++) oa[nt][j] = 0.f;

    for (int kt = 0; kt < 32; ++kt) {
        CP_WAIT0();            // tile kt resident
        __syncthreads();       // all warps past compute(kt-1); data published

        if (kt + 1 < 32) {     // issue tile kt+1 into buf (kt+1)&1
            const int nb = (kt + 1) & 1;
            const float* Ks = Kg + (size_t)((kt + 1) * 64 + lrow) * E_;
            const float* Vs = Vtg + (size_t)lrow * S_ + (kt + 1) * 64;
#pragma unroll
            for (int i = 0; i < 4; i++) {
                cpasync16(dK + nb * KVBB + i * 16, Ks + lc0 + i * 4);
                cpasync16(dV + nb * KVBB + i * 16, Vs + lc0 + i * 4);
            }
        }
        CP_COMMIT();

        const uint32_t kB = sKb + (kt & 1) * KVBB + BLANE(lane, AP);
        const uint32_t vB = sVb + (kt & 1) * KVBB + BLANE(lane, AP);

        // ---- S = Q K^T ----
        float sc[8][4];
#pragma unroll
        for (int nt = 0; nt < 8; nt++)
#pragma unroll
            for (int j = 0; j < 4; j++) sc[nt][j] = 0.f;

#pragma unroll
        for (int ks = 0; ks < 8; ks++) {
#pragma unroll
            for (int np = 0; np < 4; np++) {
                uint32_t bf[4];
                ldmx4(bf, kB + np * (16 * AP * 4) + ks * 32);
                mma8(sc[np * 2    ], qf[ks][0], qf[ks][1], qf[ks][2], qf[ks][3], bf[0], bf[1]);
                mma8(sc[np * 2 + 1], qf[ks][0], qf[ks][1], qf[ks][2], qf[ks][3], bf[2], bf[3]);
            }
        }

        // ---- online softmax ----
        float mx0 = -INFINITY, mx1 = -INFINITY;
#pragma unroll
        for (int nt = 0; nt < 8; nt++) {
            mx0 = fmaxf(mx0, fmaxf(sc[nt][0], sc[nt][1]));
            mx1 = fmaxf(mx1, fmaxf(sc[nt][2], sc[nt][3]));
        }
        mx0 = fmaxf(mx0, __shfl_xor_sync(0xffffffffu, mx0, 1));
        mx0 = fmaxf(mx0, __shfl_xor_sync(0xffffffffu, mx0, 2));
        mx1 = fmaxf(mx1, __shfl_xor_sync(0xffffffffu, mx1, 1));
        mx1 = fmaxf(mx1, __shfl_xor_sync(0xffffffffu, mx1, 2));

        const float mn0 = fmaxf(mr0, mx0);
        const float mn1 = fmaxf(mr1, mx1);
        const float c0 = __expf(mr0 - mn0);
        const float c1 = __expf(mr1 - mn1);
        mr0 = mn0; mr1 = mn1;

        float rs0 = 0.f, rs1 = 0.f;
#pragma unroll
        for (int nt = 0; nt < 8; nt++) {
            sc[nt][0] = __expf(sc[nt][0] - mn0); rs0 += sc[nt][0];
            sc[nt][1] = __expf(sc[nt][1] - mn0); rs0 += sc[nt][1];
            sc[nt][2] = __expf(sc[nt][2] - mn1); rs1 += sc[nt][2];
            sc[nt][3] = __expf(sc[nt][3] - mn1); rs1 += sc[nt][3];
        }
        rs0 += __shfl_xor_sync(0xffffffffu, rs0, 1);
        rs0 += __shfl_xor_sync(0xffffffffu, rs0, 2);
        rs1 += __shfl_xor_sync(0xffffffffu, rs1, 1);
        rs1 += __shfl_xor_sync(0xffffffffu, rs1, 2);
        lr0 = lr0 * c0 + rs0;
        lr1 = lr1 * c1 + rs1;

#pragma unroll
        for (int nt = 0; nt < 8; nt++) {
            oa[nt][0] *= c0; oa[nt][1] *= c0;
            oa[nt][2] *= c1; oa[nt][3] *= c1;
        }

        // ---- P -> smem (warp-local rows of QP region) ----
#pragma unroll
        for (int nt = 0; nt < 8; nt++) {
            const int cc = nt * 8 + 2 * tig;
            *(float2*)&QP[(r0    ) * AP + cc] = make_float2(tf32r(sc[nt][0]), tf32r(sc[nt][1]));
            *(float2*)&QP[(r0 + 8) * AP + cc] = make_float2(tf32r(sc[nt][2]), tf32r(sc[nt][3]));
        }
        __syncwarp();

        // ---- PV: oa += P @ V ----
#pragma unroll
        for (int ks = 0; ks < 8; ks++) {
            uint32_t ap[4];
            ldmx4(ap, qpL + ks * 32);
#pragma unroll
            for (int np = 0; np < 4; np++) {
                uint32_t bf[4];
                ldmx4(bf, vB + np * (16 * AP * 4) + ks * 32);
                mma8(oa[np * 2    ], ap[0], ap[1], ap[2], ap[3], bf[0], bf[1]);
                mma8(oa[np * 2 + 1], ap[0], ap[1], ap[2], ap[3], bf[2], bf[3]);
            }
        }
        __syncwarp();
    }

    // ---- epilogue: rounded ctx[b][h][s][d] ----
    const float i0 = 1.0f / lr0;
    const float i1 = 1.0f / lr1;
    float* Og = g_ctx + ((size_t)(b * H_ + h) * S_ + q0) * HD_;
#pragma unroll
    for (int nt = 0; nt < 8; nt++) {
        const int col = nt * 8 + 2 * tig;
        *(float2*)(Og + (size_t)(r0    ) * HD_ + col) =
            make_float2(tf32r(oa[nt][0] * i0), tf32r(oa[nt][1] * i0));
        *(float2*)(Og + (size_t)(r0 + 8) * HD_ + col) =
            make_float2(tf32r(oa[nt][2] * i1), tf32r(oa[nt][3] * i1));
    }
}

// ============================================================
extern "C" void kernel_launch(void* const* d_in, const int* in_sizes, int n_in,
                              void* d_out, int out_size)
{
    const float* X  = (const float*)d_in[0];
    const float* Wq = (const float*)d_in[1];
    const float* bq = (const float*)d_in[2];
    const float* Wk = (const float*)d_in[3];
    const float* bk = (const float*)d_in[4];
    const float* Wv = (const float*)d_in[5];
    const float* bv = (const float*)d_in[6];
    const float* Wo = (const float*)d_in[7];
    const float* bo = (const float*)d_in[8];
    float* out = (float*)d_out;

    cudaFuncSetAttribute(qkv_kernel,
                         cudaFuncAttributeMaxDynamicSharedMemorySize, GEMM_SMEM);
    cudaFuncSetAttribute(oproj_kernel,
                         cudaFuncAttributeMaxDynamicSharedMemorySize, GEMM_SMEM);
    cudaFuncSetAttribute(attn_kernel,
                         cudaFuncAttributeMaxDynamicSharedMemorySize, ATTN_SMEM);

    // 1. round X + weights
    prep_kernel<<<dim3(M_ * E_ / (256 * 4), 5), 256>>>(X, Wq, Wk, Wv, Wo);

    // 2. Q/K/V projections
    qkv_kernel<<<dim3(E_ / 128, M_ / 128, 3), 256, GEMM_SMEM>>>(bq, bk, bv);

    // 3. attention
    attn_kernel<<<dim3(S_ / 128, H_, B_), 256, ATTN_SMEM>>>();

    // 4. output projection
    oproj_kernel<<<dim3(E_ / 128, M_ / 128), 256, GEMM_SMEM>>>(bo, out);
}